// round 2
// baseline (speedup 1.0000x reference)
#include <cuda_runtime.h>
#include <cuda_bf16.h>
#include <cstdint>

#define NB 4096
#define NT 32              // 32 row/col tiles of 128
#define NTILES 528         // upper-triangle tile count (incl. diagonal)

// ---------------- device scratch (static: no allocation allowed) ----------------
__device__ __nv_bfloat16 g_C[(size_t)NB * 256];   // [x | -2m | 1/v | m/v]
__device__ __nv_bfloat16 g_D[(size_t)NB * 256];   // [1/v | m/v | x | -2m]
__device__ float  g_A4[NB];    // 0.25*a_i - 16
__device__ float  g_P4[NB];    // 0.25*p_i
__device__ float  g_Q[NB];     // 1/(p_i + 1e-8)
__device__ double g_pos, g_neg;

static __device__ __forceinline__ uint32_t smem_u32(const void* p) {
    uint32_t a;
    asm("{ .reg .u64 t; cvta.to.shared.u64 t, %1; cvt.u32.u64 %0, t; }" : "=r"(a) : "l"(p));
    return a;
}

// ---------------- kernel 1: prep ----------------
// one warp per row; lane handles dims {lane, lane+32}
__global__ void __launch_bounds__(128) prep_kernel(const float* __restrict__ mu,
                                                   const float* __restrict__ var) {
    int row  = blockIdx.x * 4 + (threadIdx.x >> 5);
    int lane = threadIdx.x & 31;
    float m0 = mu[row * 64 + lane], m1 = mu[row * 64 + lane + 32];
    float v0 = var[row * 64 + lane], v1 = var[row * 64 + lane + 32];
    float iv0 = 1.0f / v0, iv1 = 1.0f / v1;
    float x0 = v0 + m0 * m0, x1 = v1 + m1 * m1;
    float w0 = m0 * iv0, w1 = m1 * iv1;

    __nv_bfloat16* C = g_C + (size_t)row * 256;
    __nv_bfloat16* D = g_D + (size_t)row * 256;
    C[lane]        = __float2bfloat16(x0);
    C[lane + 32]   = __float2bfloat16(x1);
    C[64 + lane]   = __float2bfloat16(-2.0f * m0);
    C[96 + lane]   = __float2bfloat16(-2.0f * m1);
    C[128 + lane]  = __float2bfloat16(iv0);
    C[160 + lane]  = __float2bfloat16(iv1);
    C[192 + lane]  = __float2bfloat16(w0);
    C[224 + lane]  = __float2bfloat16(w1);

    D[lane]        = __float2bfloat16(iv0);
    D[lane + 32]   = __float2bfloat16(iv1);
    D[64 + lane]   = __float2bfloat16(w0);
    D[96 + lane]   = __float2bfloat16(w1);
    D[128 + lane]  = __float2bfloat16(x0);
    D[160 + lane]  = __float2bfloat16(x1);
    D[192 + lane]  = __float2bfloat16(-2.0f * m0);
    D[224 + lane]  = __float2bfloat16(-2.0f * m1);

    float pv = v0 * v1;
    float av = m0 * m0 * iv0 + m1 * m1 * iv1;
    #pragma unroll
    for (int off = 16; off; off >>= 1) {
        pv *= __shfl_xor_sync(0xffffffffu, pv, off);
        av += __shfl_xor_sync(0xffffffffu, av, off);
    }
    if (lane == 0) {
        g_A4[row] = 0.25f * av - 16.0f;
        g_P4[row] = 0.25f * pv;
        g_Q[row]  = 1.0f / (pv + 1e-8f);
    }
    if (blockIdx.x == 0 && threadIdx.x == 0) { g_pos = 0.0; g_neg = 0.0; }
}

// ---------------- kernel 2: fused symmetric GEMM + sigmoid + masked reduce ----------------
// Tile 128x128, K=256. SMEM rows padded to 264 bf16 (528 B = 33x16B, conflict-free ldmatrix).
#define ROWB 528                       // bytes per padded smem row
#define CS_OFF 0
#define DS_OFF (128 * ROWB)            // 67584
#define PAR_OFF (2 * 128 * ROWB)       // 135168
#define RED_OFF (PAR_OFF + 4096)       // 139264
#define SMEM_BYTES (RED_OFF + 64)      // 139328

__global__ void __launch_bounds__(256) fused_kernel(const int* __restrict__ labels) {
    extern __shared__ char smem[];
    uint32_t sbase = smem_u32(smem);
    int tid = threadIdx.x, lane = tid & 31, wid = tid >> 5;

    // map linear block id -> upper-triangle tile (I <= J)
    int t = blockIdx.x, I = 0;
    while (t >= NT - I) { t -= NT - I; I++; }
    int J = I + t;
    int Ibase = I * 128, Jbase = J * 128;

    float* spAI = (float*)(smem + PAR_OFF);
    float* spPI = spAI + 128;
    float* spQI = spPI + 128;
    int*   spLI = (int*)(spQI + 128);
    float* spAJ = (float*)(spLI + 128);
    float* spPJ = spAJ + 128;
    float* spQJ = spPJ + 128;
    int*   spLJ = (int*)(spQJ + 128);
    float* red  = (float*)(smem + RED_OFF);

    // stage tiles (each row: 256 bf16 = 32 x uint4)
    const uint4* srcC = (const uint4*)(g_C + (size_t)Ibase * 256);
    const uint4* srcD = (const uint4*)(g_D + (size_t)Jbase * 256);
    #pragma unroll 4
    for (int idx = tid; idx < 4096; idx += 256) {
        int row = idx >> 5, c16 = idx & 31;
        *(uint4*)(smem + CS_OFF + row * ROWB + c16 * 16) = srcC[idx];
        *(uint4*)(smem + DS_OFF + row * ROWB + c16 * 16) = srcD[idx];
    }
    if (tid < 128) {
        spAI[tid] = g_A4[Ibase + tid];
        spPI[tid] = g_P4[Ibase + tid];
        spQI[tid] = g_Q[Ibase + tid];
        spLI[tid] = labels[Ibase + tid];
    } else {
        int r = tid - 128;
        spAJ[r] = g_A4[Jbase + r];
        spPJ[r] = g_P4[Jbase + r];
        spQJ[r] = g_Q[Jbase + r];
        spLJ[r] = labels[Jbase + r];
    }
    __syncthreads();

    // warp tiling: 2 (m) x 4 (n); each warp 64x32
    int warp_m = wid & 1, warp_n = wid >> 1;

    float acc[4][4][4];
    #pragma unroll
    for (int mi = 0; mi < 4; mi++)
        #pragma unroll
        for (int ni = 0; ni < 4; ni++)
            #pragma unroll
            for (int e = 0; e < 4; e++) acc[mi][ni][e] = 0.0f;

    uint32_t csA = sbase + CS_OFF, csB = sbase + DS_OFF;

    #pragma unroll 1
    for (int k0 = 0; k0 < 256; k0 += 16) {
        uint32_t af[4][4];
        #pragma unroll
        for (int mi = 0; mi < 4; mi++) {
            int r = warp_m * 64 + mi * 16 + (lane & 15);
            uint32_t addr = csA + r * ROWB + (k0 + ((lane >> 4) << 3)) * 2;
            asm volatile("ldmatrix.sync.aligned.m8n8.x4.shared.b16 {%0,%1,%2,%3}, [%4];"
                         : "=r"(af[mi][0]), "=r"(af[mi][1]), "=r"(af[mi][2]), "=r"(af[mi][3])
                         : "r"(addr));
        }
        #pragma unroll
        for (int ni = 0; ni < 4; ni++) {
            int r = warp_n * 32 + ni * 8 + (lane & 7);
            uint32_t addr = csB + r * ROWB + (k0 + (((lane >> 3) & 1) << 3)) * 2;
            uint32_t b0, b1;
            asm volatile("ldmatrix.sync.aligned.m8n8.x2.shared.b16 {%0,%1}, [%2];"
                         : "=r"(b0), "=r"(b1) : "r"(addr));
            #pragma unroll
            for (int mi = 0; mi < 4; mi++) {
                asm volatile(
                    "mma.sync.aligned.m16n8k16.row.col.f32.bf16.bf16.f32 "
                    "{%0,%1,%2,%3}, {%4,%5,%6,%7}, {%8,%9}, {%0,%1,%2,%3};"
                    : "+f"(acc[mi][ni][0]), "+f"(acc[mi][ni][1]),
                      "+f"(acc[mi][ni][2]), "+f"(acc[mi][ni][3])
                    : "r"(af[mi][0]), "r"(af[mi][1]), "r"(af[mi][2]), "r"(af[mi][3]),
                      "r"(b0), "r"(b1));
            }
        }
    }

    // fused epilogue: sym = 0.25*Gsum + (0.25 a_i - 16) + (0.25 a_j - 16)
    //                     + 0.25 p_i q_j + 0.25 p_j q_i
    // sigmoid(sym) = 1 / (1 + exp2(-sym * log2e))
    const bool diag = (I == J);
    const float NL2E = -1.4426950408889634f;
    float pos = 0.0f, neg = 0.0f;

    #pragma unroll
    for (int mi = 0; mi < 4; mi++) {
        #pragma unroll
        for (int h = 0; h < 2; h++) {
            int r = warp_m * 64 + mi * 16 + (lane >> 2) + h * 8;
            float RA = spAI[r], RP = spPI[r], RQ = spQI[r];
            int   RL = spLI[r];
            #pragma unroll
            for (int ni = 0; ni < 4; ni++) {
                #pragma unroll
                for (int e = 0; e < 2; e++) {
                    int c = warp_n * 32 + ni * 8 + (lane & 3) * 2 + e;
                    float v = acc[mi][ni][h * 2 + e];
                    float s1 = fmaf(v, 0.25f, RA);
                    float s2 = s1 + spAJ[c];
                    float s3 = fmaf(RP, spQJ[c], s2);
                    float s4 = fmaf(spPJ[c], RQ, s3);
                    float u  = s4 * NL2E;
                    float ex;
                    asm("ex2.approx.f32 %0, %1;" : "=f"(ex) : "f"(u));
                    float den = ex + 1.0f;
                    float sg;
                    asm("rcp.approx.f32 %0, %1;" : "=f"(sg) : "f"(den));
                    bool count = (!diag) || (c > r);
                    bool same  = (RL == spLJ[c]);
                    if (count) {
                        pos += same ? sg : 0.0f;
                        neg += same ? 0.0f : sg;
                    }
                }
            }
        }
    }

    #pragma unroll
    for (int off = 16; off; off >>= 1) {
        pos += __shfl_xor_sync(0xffffffffu, pos, off);
        neg += __shfl_xor_sync(0xffffffffu, neg, off);
    }
    if (lane == 0) { red[wid] = pos; red[8 + wid] = neg; }
    __syncthreads();
    if (tid == 0) {
        double P = 0.0, Nn = 0.0;
        #pragma unroll
        for (int w = 0; w < 8; w++) { P += (double)red[w]; Nn += (double)red[8 + w]; }
        atomicAdd(&g_pos, P);
        atomicAdd(&g_neg, Nn);
    }
}

// ---------------- kernel 3: finalize ----------------
__global__ void fin_kernel(float* __restrict__ out) {
    double P  = 2.0 * g_pos;   // upper triangle counted once; full matrix is symmetric
    double Nn = 2.0 * g_neg;
    const double inv = 1.0 / ((double)NB * (double)NB);
    out[0] = (float)(P * inv);
    out[1] = (float)(Nn * inv);
    out[2] = (float)P;
    out[3] = (float)Nn;
}

// ---------------- launcher ----------------
extern "C" void kernel_launch(void* const* d_in, const int* in_sizes, int n_in,
                              void* d_out, int out_size) {
    (void)in_sizes; (void)n_in; (void)out_size;
    const float* mu     = (const float*)d_in[0];
    const float* var    = (const float*)d_in[1];
    const int*   labels = (const int*)d_in[2];
    float* out = (float*)d_out;

    cudaFuncSetAttribute(fused_kernel, cudaFuncAttributeMaxDynamicSharedMemorySize,
                         SMEM_BYTES);

    prep_kernel<<<NB / 4, 128>>>(mu, var);
    fused_kernel<<<NTILES, 256, SMEM_BYTES>>>(labels);
    fin_kernel<<<1, 1>>>(out);
}

// round 3
// speedup vs baseline: 1.3279x; 1.3279x over previous
#include <cuda_runtime.h>
#include <cuda_bf16.h>
#include <cstdint>

#define NB 4096
#define NT 32              // 32 row/col tiles of 128
#define NTILES 528         // upper-triangle tile count (incl. diagonal)

// ---------------- device scratch (static: no allocation allowed) ----------------
// C row (256 bf16): [x | -2m | 1/v | m/v], x = v + m^2
// D row needed by the GEMM is C rotated by 128 cols -> derived at staging time.
__device__ __nv_bfloat16 g_C[(size_t)NB * 256];
__device__ float  g_A8[NB];    // 0.125*a_i - 8
__device__ float  g_P8[NB];    // 0.125*p_i
__device__ float  g_Q[NB];     // 1/(p_i + 1e-8)
__device__ double g_pos, g_neg;

static __device__ __forceinline__ uint32_t smem_u32(const void* p) {
    uint32_t a;
    asm("{ .reg .u64 t; cvta.to.shared.u64 t, %1; cvt.u32.u64 %0, t; }" : "=r"(a) : "l"(p));
    return a;
}
static __device__ __forceinline__ float frcp(float x) {
    float r; asm("rcp.approx.f32 %0, %1;" : "=f"(r) : "f"(x)); return r;
}
static __device__ __forceinline__ float ftanh(float x) {
    float r; asm("tanh.approx.f32 %0, %1;" : "=f"(r) : "f"(x)); return r;
}

// ---------------- kernel 1: prep ----------------
// one warp per row; lane handles dims {lane, lane+32}
__global__ void __launch_bounds__(256) prep_kernel(const float* __restrict__ mu,
                                                   const float* __restrict__ var) {
    int row  = blockIdx.x * 8 + (threadIdx.x >> 5);
    int lane = threadIdx.x & 31;
    float m0 = mu[row * 64 + lane], m1 = mu[row * 64 + lane + 32];
    float v0 = var[row * 64 + lane], v1 = var[row * 64 + lane + 32];
    float iv0 = frcp(v0), iv1 = frcp(v1);
    float x0 = v0 + m0 * m0, x1 = v1 + m1 * m1;
    float w0 = m0 * iv0, w1 = m1 * iv1;

    __nv_bfloat16* C = g_C + (size_t)row * 256;
    C[lane]        = __float2bfloat16(x0);
    C[lane + 32]   = __float2bfloat16(x1);
    C[64 + lane]   = __float2bfloat16(-2.0f * m0);
    C[96 + lane]   = __float2bfloat16(-2.0f * m1);
    C[128 + lane]  = __float2bfloat16(iv0);
    C[160 + lane]  = __float2bfloat16(iv1);
    C[192 + lane]  = __float2bfloat16(w0);
    C[224 + lane]  = __float2bfloat16(w1);

    float pv = v0 * v1;
    float av = m0 * m0 * iv0 + m1 * m1 * iv1;
    #pragma unroll
    for (int off = 16; off; off >>= 1) {
        pv *= __shfl_xor_sync(0xffffffffu, pv, off);
        av += __shfl_xor_sync(0xffffffffu, av, off);
    }
    if (lane == 0) {
        g_A8[row] = 0.125f * av - 8.0f;
        g_P8[row] = 0.125f * pv;
        g_Q[row]  = frcp(pv + 1e-8f);
    }
    if (blockIdx.x == 0 && threadIdx.x == 0) { g_pos = 0.0; g_neg = 0.0; }
}

// ---------------- kernel 2: fused symmetric GEMM + sigmoid + masked reduce ----------------
// Tile 128x128, K=256 split into 2 chunks of 128, single-buffered smem.
// Chunk row: 128 bf16 = 256B, padded pitch 272B (17x16B -> conflict-free ldmatrix).
#define PITCH 272
#define CS_OFF 0
#define DS_OFF (128 * PITCH)           // 34816
#define PAR_OFF (2 * 128 * PITCH)      // 69632
#define RED_OFF (PAR_OFF + 4096)       // 73728
#define SMEM_BYTES (RED_OFF + 64)      // 73792

__global__ void __launch_bounds__(256, 2) fused_kernel(const int* __restrict__ labels) {
    extern __shared__ char smem[];
    uint32_t sbase = smem_u32(smem);
    int tid = threadIdx.x, lane = tid & 31, wid = tid >> 5;

    // map linear block id -> upper-triangle tile (I <= J)
    int t = blockIdx.x, I = 0;
    while (t >= NT - I) { t -= NT - I; I++; }
    int J = I + t;
    int Ibase = I * 128, Jbase = J * 128;

    float* spAI = (float*)(smem + PAR_OFF);
    float* spPI = spAI + 128;
    float* spQI = spPI + 128;
    int*   spLI = (int*)(spQI + 128);
    float* spAJ = (float*)(spLI + 128);
    float* spPJ = spAJ + 128;
    float* spQJ = spPJ + 128;
    int*   spLJ = (int*)(spQJ + 128);
    float* red  = (float*)(smem + RED_OFF);

    const char* baseI = (const char*)g_C + (size_t)Ibase * 512;
    const char* baseJ = (const char*)g_C + (size_t)Jbase * 512;

    // ---- stage chunk 0: A from C(I) chunk0, B from "D"(J) chunk0 = C(J) chunk1
    {
        int row = tid >> 4, c16 = tid & 15;          // 16 rows per pass of 256 threads
        #pragma unroll
        for (int p = 0; p < 8; p++) {
            int r = row + p * 16;
            uint32_t dA = sbase + CS_OFF + r * PITCH + c16 * 16;
            uint32_t dB = sbase + DS_OFF + r * PITCH + c16 * 16;
            const char* sA = baseI + r * 512 + c16 * 16;          // chunk0 bytes 0..255
            const char* sB = baseJ + r * 512 + 256 + c16 * 16;    // chunk1 bytes 256..511
            asm volatile("cp.async.ca.shared.global [%0], [%1], 16;" :: "r"(dA), "l"(sA));
            asm volatile("cp.async.ca.shared.global [%0], [%1], 16;" :: "r"(dB), "l"(sB));
        }
        asm volatile("cp.async.commit_group;" ::: "memory");
    }
    // params (regular loads, overlap with cp.async)
    if (tid < 128) {
        spAI[tid] = g_A8[Ibase + tid];
        spPI[tid] = g_P8[Ibase + tid];
        spQI[tid] = g_Q[Ibase + tid];
        spLI[tid] = labels[Ibase + tid];
    } else {
        int r = tid - 128;
        spAJ[r] = g_A8[Jbase + r];
        spPJ[r] = g_P8[Jbase + r];
        spQJ[r] = g_Q[Jbase + r];
        spLJ[r] = labels[Jbase + r];
    }
    asm volatile("cp.async.wait_group 0;" ::: "memory");
    __syncthreads();

    // warp tiling: 2 (m) x 4 (n); each warp 64x32
    int warp_m = wid & 1, warp_n = wid >> 1;

    float acc[4][4][4];
    #pragma unroll
    for (int mi = 0; mi < 4; mi++)
        #pragma unroll
        for (int ni = 0; ni < 4; ni++)
            #pragma unroll
            for (int e = 0; e < 4; e++) acc[mi][ni][e] = 0.0f;

    uint32_t csA = sbase + CS_OFF, csB = sbase + DS_OFF;

    #pragma unroll 1
    for (int chunk = 0; chunk < 2; chunk++) {
        #pragma unroll 1
        for (int k0 = 0; k0 < 128; k0 += 16) {
            uint32_t af[4][4];
            #pragma unroll
            for (int mi = 0; mi < 4; mi++) {
                int r = warp_m * 64 + mi * 16 + (lane & 15);
                uint32_t addr = csA + r * PITCH + (k0 + ((lane >> 4) << 3)) * 2;
                asm volatile("ldmatrix.sync.aligned.m8n8.x4.shared.b16 {%0,%1,%2,%3}, [%4];"
                             : "=r"(af[mi][0]), "=r"(af[mi][1]), "=r"(af[mi][2]), "=r"(af[mi][3])
                             : "r"(addr));
            }
            #pragma unroll
            for (int ni = 0; ni < 4; ni++) {
                int r = warp_n * 32 + ni * 8 + (lane & 7);
                uint32_t addr = csB + r * PITCH + (k0 + (((lane >> 3) & 1) << 3)) * 2;
                uint32_t b0, b1;
                asm volatile("ldmatrix.sync.aligned.m8n8.x2.shared.b16 {%0,%1}, [%2];"
                             : "=r"(b0), "=r"(b1) : "r"(addr));
                #pragma unroll
                for (int mi = 0; mi < 4; mi++) {
                    asm volatile(
                        "mma.sync.aligned.m16n8k16.row.col.f32.bf16.bf16.f32 "
                        "{%0,%1,%2,%3}, {%4,%5,%6,%7}, {%8,%9}, {%0,%1,%2,%3};"
                        : "+f"(acc[mi][ni][0]), "+f"(acc[mi][ni][1]),
                          "+f"(acc[mi][ni][2]), "+f"(acc[mi][ni][3])
                        : "r"(af[mi][0]), "r"(af[mi][1]), "r"(af[mi][2]), "r"(af[mi][3]),
                          "r"(b0), "r"(b1));
                }
            }
        }

        if (chunk == 0) {
            // ---- stage chunk 1: A from C(I) chunk1, B from C(J) chunk0
            __syncthreads();   // everyone done reading buffer 0
            int row = tid >> 4, c16 = tid & 15;
            #pragma unroll
            for (int p = 0; p < 8; p++) {
                int r = row + p * 16;
                uint32_t dA = sbase + CS_OFF + r * PITCH + c16 * 16;
                uint32_t dB = sbase + DS_OFF + r * PITCH + c16 * 16;
                const char* sA = baseI + r * 512 + 256 + c16 * 16;
                const char* sB = baseJ + r * 512 + c16 * 16;
                asm volatile("cp.async.ca.shared.global [%0], [%1], 16;" :: "r"(dA), "l"(sA));
                asm volatile("cp.async.ca.shared.global [%0], [%1], 16;" :: "r"(dB), "l"(sB));
            }
            asm volatile("cp.async.commit_group;" ::: "memory");
            asm volatile("cp.async.wait_group 0;" ::: "memory");
            __syncthreads();
        }
    }

    // fused epilogue (half-scale form for tanh sigmoid):
    // sym/2 = 0.125*Gsum + A8_i + A8_j + P8_i*Q_j + P8_j*Q_i
    // sigmoid(sym) = 0.5 + 0.5*tanh(sym/2)
    const bool diag = (I == J);
    float pos = 0.0f, neg = 0.0f;

    #pragma unroll
    for (int mi = 0; mi < 4; mi++) {
        #pragma unroll
        for (int h = 0; h < 2; h++) {
            int r = warp_m * 64 + mi * 16 + (lane >> 2) + h * 8;
            float RA = spAI[r], RP = spPI[r], RQ = spQI[r];
            int   RL = spLI[r];
            #pragma unroll
            for (int ni = 0; ni < 4; ni++) {
                #pragma unroll
                for (int e = 0; e < 2; e++) {
                    int c = warp_n * 32 + ni * 8 + (lane & 3) * 2 + e;
                    float v = acc[mi][ni][h * 2 + e];
                    float s = fmaf(v, 0.125f, RA);
                    s += spAJ[c];
                    s = fmaf(RP, spQJ[c], s);
                    s = fmaf(spPJ[c], RQ, s);
                    float sg = fmaf(ftanh(s), 0.5f, 0.5f);
                    bool count = (!diag) || (c > r);
                    bool same  = (RL == spLJ[c]);
                    if (count) {
                        pos += same ? sg : 0.0f;
                        neg += same ? 0.0f : sg;
                    }
                }
            }
        }
    }

    #pragma unroll
    for (int off = 16; off; off >>= 1) {
        pos += __shfl_xor_sync(0xffffffffu, pos, off);
        neg += __shfl_xor_sync(0xffffffffu, neg, off);
    }
    if (lane == 0) { red[wid] = pos; red[8 + wid] = neg; }
    __syncthreads();
    if (tid == 0) {
        double P = 0.0, Nn = 0.0;
        #pragma unroll
        for (int w = 0; w < 8; w++) { P += (double)red[w]; Nn += (double)red[8 + w]; }
        atomicAdd(&g_pos, P);
        atomicAdd(&g_neg, Nn);
    }
}

// ---------------- kernel 3: finalize ----------------
__global__ void fin_kernel(float* __restrict__ out) {
    double P  = 2.0 * g_pos;   // upper triangle counted once; full matrix is symmetric
    double Nn = 2.0 * g_neg;
    const double inv = 1.0 / ((double)NB * (double)NB);
    out[0] = (float)(P * inv);
    out[1] = (float)(Nn * inv);
    out[2] = (float)P;
    out[3] = (float)Nn;
}

// ---------------- launcher ----------------
extern "C" void kernel_launch(void* const* d_in, const int* in_sizes, int n_in,
                              void* d_out, int out_size) {
    (void)in_sizes; (void)n_in; (void)out_size;
    const float* mu     = (const float*)d_in[0];
    const float* var    = (const float*)d_in[1];
    const int*   labels = (const int*)d_in[2];
    float* out = (float*)d_out;

    cudaFuncSetAttribute(fused_kernel, cudaFuncAttributeMaxDynamicSharedMemorySize,
                         SMEM_BYTES);

    prep_kernel<<<NB / 8, 256>>>(mu, var);
    fused_kernel<<<NTILES, 256, SMEM_BYTES>>>(labels);
    fin_kernel<<<1, 1>>>(out);
}

// round 4
// speedup vs baseline: 1.3395x; 1.0087x over previous
#include <cuda_runtime.h>
#include <cuda_fp16.h>
#include <cstdint>

#define NB 4096
#define NT 32              // 32 row/col tiles of 128
#define NTILES 528         // upper-triangle tile count (incl. diagonal)

// ---------------- device scratch (static: no allocation allowed) ----------------
// C row (256 fp16): [x | -2m | 1/v | m/v], x = v + m^2
// "D" row needed by the GEMM is C rotated by 128 cols -> derived at staging time.
__device__ __half g_C[(size_t)NB * 256];
__device__ float  g_A8[NB];    // 0.125*a_i - 8
__device__ float  g_P8[NB];    // 0.125*p_i
__device__ float  g_Q[NB];     // 1/(p_i + 1e-8)
__device__ double g_pos, g_neg;

static __device__ __forceinline__ uint32_t smem_u32(const void* p) {
    uint32_t a;
    asm("{ .reg .u64 t; cvta.to.shared.u64 t, %1; cvt.u32.u64 %0, t; }" : "=r"(a) : "l"(p));
    return a;
}
static __device__ __forceinline__ float frcp(float x) {
    float r; asm("rcp.approx.f32 %0, %1;" : "=f"(r) : "f"(x)); return r;
}
static __device__ __forceinline__ float ftanh(float x) {
    float r; asm("tanh.approx.f32 %0, %1;" : "=f"(r) : "f"(x)); return r;
}

// ---------------- kernel 1: prep ----------------
// 4 lanes per row; each lane owns 16 dims via 4+4 independent float4 loads.
__global__ void __launch_bounds__(256) prep_kernel(const float* __restrict__ mu,
                                                   const float* __restrict__ var) {
    int gtid = blockIdx.x * 256 + threadIdx.x;
    int row = gtid >> 2, l4 = gtid & 3;          // dims [l4*16, l4*16+16)
    const float4* m4 = (const float4*)(mu  + (size_t)row * 64) + l4 * 4;
    const float4* v4 = (const float4*)(var + (size_t)row * 64) + l4 * 4;

    float m[16], v[16];
    #pragma unroll
    for (int q = 0; q < 4; q++) {
        float4 t = m4[q];
        m[q * 4] = t.x; m[q * 4 + 1] = t.y; m[q * 4 + 2] = t.z; m[q * 4 + 3] = t.w;
    }
    #pragma unroll
    for (int q = 0; q < 4; q++) {
        float4 t = v4[q];
        v[q * 4] = t.x; v[q * 4 + 1] = t.y; v[q * 4 + 2] = t.z; v[q * 4 + 3] = t.w;
    }

    float x[16], n2m[16], iv[16], w[16];
    float pv = 1.0f, av = 0.0f;
    #pragma unroll
    for (int d = 0; d < 16; d++) {
        iv[d]  = frcp(v[d]);
        x[d]   = v[d] + m[d] * m[d];
        n2m[d] = -2.0f * m[d];
        w[d]   = m[d] * iv[d];
        pv *= v[d];
        av = fmaf(m[d] * m[d], iv[d], av);
    }

    // pack 16 fp16 per feature block as 2 x uint4 and store
    uint4* crow = (uint4*)(g_C + (size_t)row * 256);   // 32 uint4 per row
    const float* blocks[4] = {x, n2m, iv, w};
    #pragma unroll
    for (int b = 0; b < 4; b++) {
        const float* s = blocks[b];
        __half2 h[8];
        #pragma unroll
        for (int j = 0; j < 8; j++) h[j] = __floats2half2_rn(s[2 * j], s[2 * j + 1]);
        uint4* u = (uint4*)h;
        crow[b * 8 + l4 * 2]     = u[0];
        crow[b * 8 + l4 * 2 + 1] = u[1];
    }

    // reduce p, a over the 4 lanes of this row
    pv *= __shfl_xor_sync(0xffffffffu, pv, 1);
    av += __shfl_xor_sync(0xffffffffu, av, 1);
    pv *= __shfl_xor_sync(0xffffffffu, pv, 2);
    av += __shfl_xor_sync(0xffffffffu, av, 2);
    if (l4 == 0) {
        g_A8[row] = 0.125f * av - 8.0f;
        g_P8[row] = 0.125f * pv;
        g_Q[row]  = frcp(pv + 1e-8f);
    }
    if (gtid == 0) { g_pos = 0.0; g_neg = 0.0; }
}

// ---------------- kernel 2: fused symmetric GEMM + sigmoid + masked reduce ----------------
// Tile 128x128, K=256 in 2 chunks of 128, single-buffered smem, 4 warps (64x64 each),
// fp16 accumulators (once-per-HMMA rounding keeps error negligible).
#define PITCH 272
#define CS_OFF 0
#define DS_OFF (128 * PITCH)           // 34816
#define PAR_OFF (2 * 128 * PITCH)      // 69632
#define RED_OFF (PAR_OFF + 4096)       // 73728
#define SMEM_BYTES (RED_OFF + 64)      // 73792

static __device__ __forceinline__ void gemm_chunk(
    uint32_t csA, uint32_t csB, int lane, int warp_m, int warp_n,
    uint32_t (&h)[4][8][2])
{
    #pragma unroll 2
    for (int k0 = 0; k0 < 128; k0 += 16) {
        uint32_t af[4][4];
        #pragma unroll
        for (int mi = 0; mi < 4; mi++) {
            int r = warp_m * 64 + mi * 16 + (lane & 15);
            uint32_t addr = csA + r * PITCH + (k0 + ((lane >> 4) << 3)) * 2;
            asm volatile("ldmatrix.sync.aligned.m8n8.x4.shared.b16 {%0,%1,%2,%3}, [%4];"
                         : "=r"(af[mi][0]), "=r"(af[mi][1]), "=r"(af[mi][2]), "=r"(af[mi][3])
                         : "r"(addr));
        }
        #pragma unroll
        for (int ni = 0; ni < 8; ni++) {
            int r = warp_n * 64 + ni * 8 + (lane & 7);
            uint32_t addr = csB + r * PITCH + (k0 + (((lane >> 3) & 1) << 3)) * 2;
            uint32_t b0, b1;
            asm volatile("ldmatrix.sync.aligned.m8n8.x2.shared.b16 {%0,%1}, [%2];"
                         : "=r"(b0), "=r"(b1) : "r"(addr));
            #pragma unroll
            for (int mi = 0; mi < 4; mi++) {
                asm volatile(
                    "mma.sync.aligned.m16n8k16.row.col.f16.f16.f16.f16 "
                    "{%0,%1}, {%2,%3,%4,%5}, {%6,%7}, {%0,%1};"
                    : "+r"(h[mi][ni][0]), "+r"(h[mi][ni][1])
                    : "r"(af[mi][0]), "r"(af[mi][1]), "r"(af[mi][2]), "r"(af[mi][3]),
                      "r"(b0), "r"(b1));
            }
        }
    }
}

__global__ void __launch_bounds__(128, 3) fused_kernel(const int* __restrict__ labels) {
    extern __shared__ char smem[];
    uint32_t sbase = smem_u32(smem);
    int tid = threadIdx.x, lane = tid & 31, wid = tid >> 5;

    // map linear block id -> upper-triangle tile (I <= J)
    int t = blockIdx.x, I = 0;
    while (t >= NT - I) { t -= NT - I; I++; }
    int J = I + t;
    int Ibase = I * 128, Jbase = J * 128;

    float* spAI = (float*)(smem + PAR_OFF);
    float* spPI = spAI + 128;
    float* spQI = spPI + 128;
    int*   spLI = (int*)(spQI + 128);
    float* spAJ = (float*)(spLI + 128);
    float* spPJ = spAJ + 128;
    float* spQJ = spPJ + 128;
    int*   spLJ = (int*)(spQJ + 128);
    float* red  = (float*)(smem + RED_OFF);

    const char* baseI = (const char*)g_C + (size_t)Ibase * 512;
    const char* baseJ = (const char*)g_C + (size_t)Jbase * 512;

    // ---- stage chunk 0: A = C(I) bytes [0,256), B = C(J) bytes [256,512)
    {
        int row0 = tid >> 4, c16 = tid & 15;
        #pragma unroll
        for (int p = 0; p < 16; p++) {
            int r = row0 + p * 8;
            uint32_t dA = sbase + CS_OFF + r * PITCH + c16 * 16;
            uint32_t dB = sbase + DS_OFF + r * PITCH + c16 * 16;
            const char* sA = baseI + r * 512 + c16 * 16;
            const char* sB = baseJ + r * 512 + 256 + c16 * 16;
            asm volatile("cp.async.ca.shared.global [%0], [%1], 16;" :: "r"(dA), "l"(sA));
            asm volatile("cp.async.ca.shared.global [%0], [%1], 16;" :: "r"(dB), "l"(sB));
        }
        asm volatile("cp.async.commit_group;" ::: "memory");
    }
    // params (regular loads overlap the cp.async)
    if (tid < 128) {
        spAI[tid] = g_A8[Ibase + tid];
        spPI[tid] = g_P8[Ibase + tid];
        spQI[tid] = g_Q[Ibase + tid];
        spLI[tid] = labels[Ibase + tid];
        spAJ[tid] = g_A8[Jbase + tid];
        spPJ[tid] = g_P8[Jbase + tid];
        spQJ[tid] = g_Q[Jbase + tid];
        spLJ[tid] = labels[Jbase + tid];
    }
    asm volatile("cp.async.wait_group 0;" ::: "memory");
    __syncthreads();

    int warp_m = wid & 1, warp_n = wid >> 1;

    uint32_t h[4][8][2];
    #pragma unroll
    for (int mi = 0; mi < 4; mi++)
        #pragma unroll
        for (int ni = 0; ni < 8; ni++) { h[mi][ni][0] = 0u; h[mi][ni][1] = 0u; }

    uint32_t csA = sbase + CS_OFF, csB = sbase + DS_OFF;

    gemm_chunk(csA, csB, lane, warp_m, warp_n, h);

    // ---- stage chunk 1: A = C(I) bytes [256,512), B = C(J) bytes [0,256)
    __syncthreads();
    {
        int row0 = tid >> 4, c16 = tid & 15;
        #pragma unroll
        for (int p = 0; p < 16; p++) {
            int r = row0 + p * 8;
            uint32_t dA = sbase + CS_OFF + r * PITCH + c16 * 16;
            uint32_t dB = sbase + DS_OFF + r * PITCH + c16 * 16;
            const char* sA = baseI + r * 512 + 256 + c16 * 16;
            const char* sB = baseJ + r * 512 + c16 * 16;
            asm volatile("cp.async.ca.shared.global [%0], [%1], 16;" :: "r"(dA), "l"(sA));
            asm volatile("cp.async.ca.shared.global [%0], [%1], 16;" :: "r"(dB), "l"(sB));
        }
        asm volatile("cp.async.commit_group;" ::: "memory");
        asm volatile("cp.async.wait_group 0;" ::: "memory");
    }
    __syncthreads();

    gemm_chunk(csA, csB, lane, warp_m, warp_n, h);

    // fused epilogue (half-scale form for tanh sigmoid):
    // sym/2 = 0.125*Gsum + A8_i + A8_j + P8_i*Q_j + P8_j*Q_i
    // sigmoid(sym) = 0.5 + 0.5*tanh(sym/2)
    const bool diag = (I == J);
    float pos = 0.0f, neg = 0.0f;

    #pragma unroll
    for (int mi = 0; mi < 4; mi++) {
        #pragma unroll
        for (int k = 0; k < 2; k++) {
            int r = warp_m * 64 + mi * 16 + (lane >> 2) + k * 8;
            float RA = spAI[r], RP = spPI[r], RQ = spQI[r];
            int   RL = spLI[r];
            #pragma unroll
            for (int ni = 0; ni < 8; ni++) {
                __half2 hv = *reinterpret_cast<__half2*>(&h[mi][ni][k]);
                float2 f = __half22float2(hv);
                int c0 = warp_n * 64 + ni * 8 + (lane & 3) * 2;
                #pragma unroll
                for (int e = 0; e < 2; e++) {
                    int c = c0 + e;
                    float v = e ? f.y : f.x;
                    float s = fmaf(v, 0.125f, RA);
                    s += spAJ[c];
                    s = fmaf(RP, spQJ[c], s);
                    s = fmaf(spPJ[c], RQ, s);
                    float sg = fmaf(ftanh(s), 0.5f, 0.5f);
                    bool count = (!diag) || (c > r);
                    bool same  = (RL == spLJ[c]);
                    if (count) {
                        pos += same ? sg : 0.0f;
                        neg += same ? 0.0f : sg;
                    }
                }
            }
        }
    }

    #pragma unroll
    for (int off = 16; off; off >>= 1) {
        pos += __shfl_xor_sync(0xffffffffu, pos, off);
        neg += __shfl_xor_sync(0xffffffffu, neg, off);
    }
    if (lane == 0) { red[wid] = pos; red[4 + wid] = neg; }
    __syncthreads();
    if (tid == 0) {
        double P = 0.0, Nn = 0.0;
        #pragma unroll
        for (int w = 0; w < 4; w++) { P += (double)red[w]; Nn += (double)red[4 + w]; }
        atomicAdd(&g_pos, P);
        atomicAdd(&g_neg, Nn);
    }
}

// ---------------- kernel 3: finalize ----------------
__global__ void fin_kernel(float* __restrict__ out) {
    double P  = 2.0 * g_pos;   // upper triangle counted once; full matrix is symmetric
    double Nn = 2.0 * g_neg;
    const double inv = 1.0 / ((double)NB * (double)NB);
    out[0] = (float)(P * inv);
    out[1] = (float)(Nn * inv);
    out[2] = (float)P;
    out[3] = (float)Nn;
}

// ---------------- launcher ----------------
extern "C" void kernel_launch(void* const* d_in, const int* in_sizes, int n_in,
                              void* d_out, int out_size) {
    (void)in_sizes; (void)n_in; (void)out_size;
    const float* mu     = (const float*)d_in[0];
    const float* var    = (const float*)d_in[1];
    const int*   labels = (const int*)d_in[2];
    float* out = (float*)d_out;

    cudaFuncSetAttribute(fused_kernel, cudaFuncAttributeMaxDynamicSharedMemorySize,
                         SMEM_BYTES);

    prep_kernel<<<NB / 64, 256>>>(mu, var);
    fused_kernel<<<NTILES, 128, SMEM_BYTES>>>(labels);
    fin_kernel<<<1, 1>>>(out);
}

// round 5
// speedup vs baseline: 1.3527x; 1.0099x over previous
#include <cuda_runtime.h>
#include <cuda_fp16.h>
#include <cstdint>

#define NB 4096
#define NT 32              // 32 row/col tiles of 128
#define NTILES 528         // upper-triangle tile count (incl. diagonal)

// ---------------- device scratch (static: no allocation allowed) ----------------
// C row (256 fp16): [x | -2m | 1/v | m/v], x = v + m^2
// "D" row needed by the GEMM is C rotated by 128 cols -> derived at staging time.
__device__ __half g_C[(size_t)NB * 256];
__device__ float  g_A8[NB];    // 0.125*a_i - 8
__device__ float  g_P8[NB];    // 0.125*p_i
__device__ float  g_Q[NB];     // 1/(p_i + 1e-8)
__device__ double g_pos, g_neg;
// persistent-kernel coordination (self-resetting across graph replays)
__device__ unsigned g_arrive = 0, g_done = 0, g_ticket = 0;
__device__ volatile unsigned g_release = 0;

static __device__ __forceinline__ uint32_t smem_u32(const void* p) {
    uint32_t a;
    asm("{ .reg .u64 t; cvta.to.shared.u64 t, %1; cvt.u32.u64 %0, t; }" : "=r"(a) : "l"(p));
    return a;
}
static __device__ __forceinline__ float frcp(float x) {
    float r; asm("rcp.approx.f32 %0, %1;" : "=f"(r) : "f"(x)); return r;
}
static __device__ __forceinline__ float ftanh(float x) {
    float r; asm("tanh.approx.f32 %0, %1;" : "=f"(r) : "f"(x)); return r;
}

// smem layout: two 128x128 fp16 chunk buffers (pitch 272B), params, reduce scratch
#define PITCH 272
#define CS_OFF 0
#define DS_OFF (128 * PITCH)           // 34816
#define PAR_OFF (2 * 128 * PITCH)      // 69632
#define RED_OFF (PAR_OFF + 4096)       // 73728
#define SMEM_BYTES (RED_OFF + 64)      // 73792

static __device__ __forceinline__ void gemm_chunk(
    uint32_t csA, uint32_t csB, int lane, int warp_m, int warp_n,
    uint32_t (&h)[4][8][2])
{
    #pragma unroll 2
    for (int k0 = 0; k0 < 128; k0 += 16) {
        uint32_t af[4][4];
        #pragma unroll
        for (int mi = 0; mi < 4; mi++) {
            int r = warp_m * 64 + mi * 16 + (lane & 15);
            uint32_t addr = csA + r * PITCH + (k0 + ((lane >> 4) << 3)) * 2;
            asm volatile("ldmatrix.sync.aligned.m8n8.x4.shared.b16 {%0,%1,%2,%3}, [%4];"
                         : "=r"(af[mi][0]), "=r"(af[mi][1]), "=r"(af[mi][2]), "=r"(af[mi][3])
                         : "r"(addr));
        }
        #pragma unroll
        for (int ni = 0; ni < 8; ni++) {
            int r = warp_n * 64 + ni * 8 + (lane & 7);
            uint32_t addr = csB + r * PITCH + (k0 + (((lane >> 3) & 1) << 3)) * 2;
            uint32_t b0, b1;
            asm volatile("ldmatrix.sync.aligned.m8n8.x2.shared.b16 {%0,%1}, [%2];"
                         : "=r"(b0), "=r"(b1) : "r"(addr));
            #pragma unroll
            for (int mi = 0; mi < 4; mi++) {
                asm volatile(
                    "mma.sync.aligned.m16n8k16.row.col.f16.f16.f16.f16 "
                    "{%0,%1}, {%2,%3,%4,%5}, {%6,%7}, {%0,%1};"
                    : "+r"(h[mi][ni][0]), "+r"(h[mi][ni][1])
                    : "r"(af[mi][0]), "r"(af[mi][1]), "r"(af[mi][2]), "r"(af[mi][3]),
                      "r"(b0), "r"(b1));
            }
        }
    }
}

__global__ void __launch_bounds__(128, 3) mega_kernel(
    const float* __restrict__ mu, const float* __restrict__ var,
    const int* __restrict__ labels, float* __restrict__ out)
{
    extern __shared__ char smem[];
    uint32_t sbase = smem_u32(smem);
    int tid = threadIdx.x, lane = tid & 31, wid = tid >> 5;

    // ================= phase 0: prep (strided over CTAs) =================
    for (int r0 = blockIdx.x * 32; r0 < NB; r0 += gridDim.x * 32) {
        int row = r0 + (tid >> 2), l4 = tid & 3;   // 4 lanes per row, 16 dims each
        const float4* m4 = (const float4*)(mu  + (size_t)row * 64) + l4 * 4;
        const float4* v4 = (const float4*)(var + (size_t)row * 64) + l4 * 4;
        float m[16], v[16];
        #pragma unroll
        for (int q = 0; q < 4; q++) {
            float4 tm = m4[q];
            m[q*4] = tm.x; m[q*4+1] = tm.y; m[q*4+2] = tm.z; m[q*4+3] = tm.w;
        }
        #pragma unroll
        for (int q = 0; q < 4; q++) {
            float4 tv = v4[q];
            v[q*4] = tv.x; v[q*4+1] = tv.y; v[q*4+2] = tv.z; v[q*4+3] = tv.w;
        }
        float x[16], n2m[16], iv[16], w[16];
        float pv = 1.0f, av = 0.0f;
        #pragma unroll
        for (int d = 0; d < 16; d++) {
            iv[d]  = frcp(v[d]);
            x[d]   = v[d] + m[d] * m[d];
            n2m[d] = -2.0f * m[d];
            w[d]   = m[d] * iv[d];
            pv *= v[d];
            av = fmaf(m[d] * m[d], iv[d], av);
        }
        uint4* crow = (uint4*)(g_C + (size_t)row * 256);
        const float* blocks[4] = {x, n2m, iv, w};
        #pragma unroll
        for (int b = 0; b < 4; b++) {
            const float* s = blocks[b];
            __half2 h2[8];
            #pragma unroll
            for (int j = 0; j < 8; j++) h2[j] = __floats2half2_rn(s[2*j], s[2*j+1]);
            uint4* u = (uint4*)h2;
            crow[b * 8 + l4 * 2]     = u[0];
            crow[b * 8 + l4 * 2 + 1] = u[1];
        }
        pv *= __shfl_xor_sync(0xffffffffu, pv, 1);
        av += __shfl_xor_sync(0xffffffffu, av, 1);
        pv *= __shfl_xor_sync(0xffffffffu, pv, 2);
        av += __shfl_xor_sync(0xffffffffu, av, 2);
        if (l4 == 0) {
            g_A8[row] = 0.125f * av - 8.0f;
            g_P8[row] = 0.125f * pv;
            g_Q[row]  = frcp(pv + 1e-8f);
        }
    }

    // ================= device-wide barrier (all CTAs resident by construction) =================
    __syncthreads();
    if (tid == 0) {
        unsigned target = g_release + 1;
        __threadfence();
        unsigned a = atomicAdd(&g_arrive, 1);
        if (a == gridDim.x - 1) {
            g_arrive = 0;                 // re-arm for next replay
            g_pos = 0.0; g_neg = 0.0;     // zero accumulators for this launch
            g_ticket = gridDim.x;         // dynamic tickets start after static assignment
            __threadfence();
            atomicAdd((unsigned*)&g_release, 1);
        } else {
            while (g_release < target) __nanosleep(64);
        }
        __threadfence();
    }
    __syncthreads();

    // ================= phase 1: tile loop =================
    float* spAI = (float*)(smem + PAR_OFF);
    float* spPI = spAI + 128;
    float* spQI = spPI + 128;
    int*   spLI = (int*)(spQI + 128);
    float* spAJ = (float*)(spLI + 128);
    float* spPJ = spAJ + 128;
    float* spQJ = spPJ + 128;
    int*   spLJ = (int*)(spQJ + 128);
    float* red  = (float*)(smem + RED_OFF);
    unsigned* tick_s = (unsigned*)(red + 8);

    uint32_t csA = sbase + CS_OFF, csB = sbase + DS_OFF;
    int warp_m = wid & 1, warp_n = wid >> 1;

    float pos = 0.0f, neg = 0.0f;      // per-lane, carried across tiles
    unsigned t = blockIdx.x;

    while (t < NTILES) {
        // map ticket -> upper-triangle tile (I <= J)
        int tt = (int)t, I = 0;
        while (tt >= NT - I) { tt -= NT - I; I++; }
        int J = I + tt;
        int Ibase = I * 128, Jbase = J * 128;
        const char* baseI = (const char*)g_C + (size_t)Ibase * 512;
        const char* baseJ = (const char*)g_C + (size_t)Jbase * 512;

        __syncthreads();   // previous tile's epilogue done reading smem

        // stage chunk 0: A = C(I) bytes [0,256), B = C(J) bytes [256,512)
        {
            int row0 = tid >> 4, c16 = tid & 15;
            #pragma unroll
            for (int p = 0; p < 16; p++) {
                int r = row0 + p * 8;
                uint32_t dA = sbase + CS_OFF + r * PITCH + c16 * 16;
                uint32_t dB = sbase + DS_OFF + r * PITCH + c16 * 16;
                const char* sA = baseI + r * 512 + c16 * 16;
                const char* sB = baseJ + r * 512 + 256 + c16 * 16;
                asm volatile("cp.async.ca.shared.global [%0], [%1], 16;" :: "r"(dA), "l"(sA));
                asm volatile("cp.async.ca.shared.global [%0], [%1], 16;" :: "r"(dB), "l"(sB));
            }
            asm volatile("cp.async.commit_group;" ::: "memory");
        }
        // params overlap the cp.async
        spAI[tid] = g_A8[Ibase + tid];
        spPI[tid] = g_P8[Ibase + tid];
        spQI[tid] = g_Q[Ibase + tid];
        spLI[tid] = labels[Ibase + tid];
        spAJ[tid] = g_A8[Jbase + tid];
        spPJ[tid] = g_P8[Jbase + tid];
        spQJ[tid] = g_Q[Jbase + tid];
        spLJ[tid] = labels[Jbase + tid];
        asm volatile("cp.async.wait_group 0;" ::: "memory");
        __syncthreads();

        uint32_t h[4][8][2];
        #pragma unroll
        for (int mi = 0; mi < 4; mi++)
            #pragma unroll
            for (int ni = 0; ni < 8; ni++) { h[mi][ni][0] = 0u; h[mi][ni][1] = 0u; }

        gemm_chunk(csA, csB, lane, warp_m, warp_n, h);

        // stage chunk 1: A = C(I) bytes [256,512), B = C(J) bytes [0,256)
        __syncthreads();
        {
            int row0 = tid >> 4, c16 = tid & 15;
            #pragma unroll
            for (int p = 0; p < 16; p++) {
                int r = row0 + p * 8;
                uint32_t dA = sbase + CS_OFF + r * PITCH + c16 * 16;
                uint32_t dB = sbase + DS_OFF + r * PITCH + c16 * 16;
                const char* sA = baseI + r * 512 + 256 + c16 * 16;
                const char* sB = baseJ + r * 512 + c16 * 16;
                asm volatile("cp.async.ca.shared.global [%0], [%1], 16;" :: "r"(dA), "l"(sA));
                asm volatile("cp.async.ca.shared.global [%0], [%1], 16;" :: "r"(dB), "l"(sB));
            }
            asm volatile("cp.async.commit_group;" ::: "memory");
        }
        if (tid == 0) *tick_s = atomicAdd(&g_ticket, 1);   // fetch next tile early
        asm volatile("cp.async.wait_group 0;" ::: "memory");
        __syncthreads();

        gemm_chunk(csA, csB, lane, warp_m, warp_n, h);

        // fused epilogue: sym/2 = 0.125*Gsum + A8_i + A8_j + P8_i*Q_j + P8_j*Q_i
        // sigmoid(sym) = 0.5 + 0.5*tanh(sym/2)
        const bool diag = (I == J);
        #pragma unroll
        for (int mi = 0; mi < 4; mi++) {
            #pragma unroll
            for (int k = 0; k < 2; k++) {
                int r = warp_m * 64 + mi * 16 + (lane >> 2) + k * 8;
                float RA = spAI[r], RP = spPI[r], RQ = spQI[r];
                int   RL = spLI[r];
                #pragma unroll
                for (int ni = 0; ni < 8; ni++) {
                    __half2 hv = *reinterpret_cast<__half2*>(&h[mi][ni][k]);
                    float2 f = __half22float2(hv);
                    int c0 = warp_n * 64 + ni * 8 + (lane & 3) * 2;
                    #pragma unroll
                    for (int e = 0; e < 2; e++) {
                        int c = c0 + e;
                        float vv = e ? f.y : f.x;
                        float s = fmaf(vv, 0.125f, RA);
                        s += spAJ[c];
                        s = fmaf(RP, spQJ[c], s);
                        s = fmaf(spPJ[c], RQ, s);
                        float sg = fmaf(ftanh(s), 0.5f, 0.5f);
                        bool count = (!diag) || (c > r);
                        bool same  = (RL == spLJ[c]);
                        if (count) {
                            pos += same ? sg : 0.0f;
                            neg += same ? 0.0f : sg;
                        }
                    }
                }
            }
        }

        t = *tick_s;   // written before the pre-gemm sync -> safe to read
    }

    // ================= final reduce + output by last CTA =================
    #pragma unroll
    for (int off = 16; off; off >>= 1) {
        pos += __shfl_xor_sync(0xffffffffu, pos, off);
        neg += __shfl_xor_sync(0xffffffffu, neg, off);
    }
    __syncthreads();   // smem free for the reduce scratch
    if (lane == 0) { red[wid] = pos; red[4 + wid] = neg; }
    __syncthreads();
    if (tid == 0) {
        double P = 0.0, Nn = 0.0;
        #pragma unroll
        for (int w = 0; w < 4; w++) { P += (double)red[w]; Nn += (double)red[4 + w]; }
        atomicAdd(&g_pos, P);
        atomicAdd(&g_neg, Nn);
        __threadfence();
        unsigned d = atomicAdd(&g_done, 1);
        if (d == gridDim.x - 1) {
            double TP = 2.0 * atomicAdd(&g_pos, 0.0);   // read full totals
            double TN = 2.0 * atomicAdd(&g_neg, 0.0);
            const double inv = 1.0 / ((double)NB * (double)NB);
            out[0] = (float)(TP * inv);
            out[1] = (float)(TN * inv);
            out[2] = (float)TP;
            out[3] = (float)TN;
            g_done = 0;                                  // re-arm for next replay
        }
    }
}

// ---------------- launcher ----------------
extern "C" void kernel_launch(void* const* d_in, const int* in_sizes, int n_in,
                              void* d_out, int out_size) {
    (void)in_sizes; (void)n_in; (void)out_size;
    const float* mu     = (const float*)d_in[0];
    const float* var    = (const float*)d_in[1];
    const int*   labels = (const int*)d_in[2];
    float* out = (float*)d_out;

    cudaFuncSetAttribute(mega_kernel, cudaFuncAttributeMaxDynamicSharedMemorySize,
                         SMEM_BYTES);
    int occ = 0, sms = 0, dev = 0;
    cudaGetDevice(&dev);
    cudaOccupancyMaxActiveBlocksPerMultiprocessor(&occ, mega_kernel, 128, SMEM_BYTES);
    cudaDeviceGetAttribute(&sms, cudaDevAttrMultiProcessorCount, dev);
    int grid = occ * sms;
    if (grid > NTILES) grid = NTILES;
    if (grid < 1) grid = 1;

    mega_kernel<<<grid, 128, SMEM_BYTES>>>(mu, var, labels, out);
}

// round 6
// speedup vs baseline: 1.3708x; 1.0134x over previous
#include <cuda_runtime.h>
#include <cuda_fp16.h>
#include <cstdint>

#define NB 4096
#define NT 32               // 32x32 grid of 128x128 tiles
#define NTILES 528          // upper-triangle 128x128 tiles
#define NITEMS 1056         // each tile split into two 128x64 half-tiles

// ---------------- device scratch (static: no allocation allowed) ----------------
// C row (256 fp16): [x | -2m | 1/v | m/v], x = v + m^2
// "D" row needed by the GEMM is C rotated by 128 cols -> derived at staging time.
__device__ __half g_C[(size_t)NB * 256];
__device__ float  g_A8[NB];    // 0.125*a_i - 8
__device__ float  g_P8[NB];    // 0.125*p_i
__device__ float  g_Q[NB];     // 1/(p_i + 1e-8)
__device__ double g_pos, g_neg;
// persistent-kernel coordination (self-resetting across graph replays)
__device__ unsigned g_arrive = 0, g_done = 0, g_ticket = 0;
__device__ volatile unsigned g_release = 0;

static __device__ __forceinline__ uint32_t smem_u32(const void* p) {
    uint32_t a;
    asm("{ .reg .u64 t; cvta.to.shared.u64 t, %1; cvt.u32.u64 %0, t; }" : "=r"(a) : "l"(p));
    return a;
}
static __device__ __forceinline__ float frcp(float x) {
    float r; asm("rcp.approx.f32 %0, %1;" : "=f"(r) : "f"(x)); return r;
}
static __device__ __forceinline__ float ftanh(float x) {
    float r; asm("tanh.approx.f32 %0, %1;" : "=f"(r) : "f"(x)); return r;
}

// smem layout: A chunk 128x128fp16 (pitch 272B), B chunk 64x128fp16, params, scratch
#define PITCH 272
#define CS_OFF 0                       // A: 128*272 = 34816
#define DS_OFF 34816                   // B: 64*272  = 17408
#define PAR_OFF 52224
#define RED_OFF (PAR_OFF + 3072)       // 55296
#define SMEM_BYTES (RED_OFF + 64)      // 55360

// warp tile 64x32 inside the 128x64 item (warp_m, warp_n in {0,1})
static __device__ __forceinline__ void gemm_chunk(
    uint32_t csA, uint32_t csB, int lane, int warp_m, int warp_n,
    uint32_t (&h)[4][4][2])
{
    #pragma unroll 2
    for (int k0 = 0; k0 < 128; k0 += 16) {
        uint32_t af[4][4];
        #pragma unroll
        for (int mi = 0; mi < 4; mi++) {
            int r = warp_m * 64 + mi * 16 + (lane & 15);
            uint32_t addr = csA + r * PITCH + (k0 + ((lane >> 4) << 3)) * 2;
            asm volatile("ldmatrix.sync.aligned.m8n8.x4.shared.b16 {%0,%1,%2,%3}, [%4];"
                         : "=r"(af[mi][0]), "=r"(af[mi][1]), "=r"(af[mi][2]), "=r"(af[mi][3])
                         : "r"(addr));
        }
        #pragma unroll
        for (int ni = 0; ni < 4; ni++) {
            int r = warp_n * 32 + ni * 8 + (lane & 7);
            uint32_t addr = csB + r * PITCH + (k0 + (((lane >> 3) & 1) << 3)) * 2;
            uint32_t b0, b1;
            asm volatile("ldmatrix.sync.aligned.m8n8.x2.shared.b16 {%0,%1}, [%2];"
                         : "=r"(b0), "=r"(b1) : "r"(addr));
            #pragma unroll
            for (int mi = 0; mi < 4; mi++) {
                asm volatile(
                    "mma.sync.aligned.m16n8k16.row.col.f16.f16.f16.f16 "
                    "{%0,%1}, {%2,%3,%4,%5}, {%6,%7}, {%0,%1};"
                    : "+r"(h[mi][ni][0]), "+r"(h[mi][ni][1])
                    : "r"(af[mi][0]), "r"(af[mi][1]), "r"(af[mi][2]), "r"(af[mi][3]),
                      "r"(b0), "r"(b1));
            }
        }
    }
}

__global__ void __launch_bounds__(128, 4) mega_kernel(
    const float* __restrict__ mu, const float* __restrict__ var,
    const int* __restrict__ labels, float* __restrict__ out)
{
    extern __shared__ char smem[];
    uint32_t sbase = smem_u32(smem);
    int tid = threadIdx.x, lane = tid & 31, wid = tid >> 5;

    // ================= phase 0: prep (8 rows per CTA pass, 16 lanes/row) =================
    for (int row0 = blockIdx.x * 8; row0 < NB; row0 += gridDim.x * 8) {
        int row = row0 + (tid >> 4), l16 = tid & 15;   // dims [l16*4, l16*4+4)
        float4 m4 = ((const float4*)(mu  + (size_t)row * 64))[l16];
        float4 v4 = ((const float4*)(var + (size_t)row * 64))[l16];
        float m[4] = {m4.x, m4.y, m4.z, m4.w};
        float v[4] = {v4.x, v4.y, v4.z, v4.w};
        float x[4], n2m[4], iv[4], w[4];
        float pv = 1.0f, av = 0.0f;
        #pragma unroll
        for (int d = 0; d < 4; d++) {
            iv[d]  = frcp(v[d]);
            x[d]   = v[d] + m[d] * m[d];
            n2m[d] = -2.0f * m[d];
            w[d]   = m[d] * iv[d];
            pv *= v[d];
            av = fmaf(m[d] * m[d], iv[d], av);
        }
        uint2* crow = (uint2*)(g_C + (size_t)row * 256);   // 64 x uint2 per row
        const float* blocks[4] = {x, n2m, iv, w};
        #pragma unroll
        for (int b = 0; b < 4; b++) {
            const float* s = blocks[b];
            __half2 h2[2] = {__floats2half2_rn(s[0], s[1]), __floats2half2_rn(s[2], s[3])};
            crow[b * 16 + l16] = *(uint2*)h2;
        }
        pv *= __shfl_xor_sync(0xffffffffu, pv, 1);
        av += __shfl_xor_sync(0xffffffffu, av, 1);
        pv *= __shfl_xor_sync(0xffffffffu, pv, 2);
        av += __shfl_xor_sync(0xffffffffu, av, 2);
        pv *= __shfl_xor_sync(0xffffffffu, pv, 4);
        av += __shfl_xor_sync(0xffffffffu, av, 4);
        pv *= __shfl_xor_sync(0xffffffffu, pv, 8);
        av += __shfl_xor_sync(0xffffffffu, av, 8);
        if (l16 == 0) {
            g_A8[row] = 0.125f * av - 8.0f;
            g_P8[row] = 0.125f * pv;
            g_Q[row]  = frcp(pv + 1e-8f);
        }
    }

    // ================= device-wide barrier (all CTAs resident by construction) =================
    __syncthreads();
    if (tid == 0) {
        unsigned target = g_release + 1;
        __threadfence();
        unsigned a = atomicAdd(&g_arrive, 1);
        if (a == gridDim.x - 1) {
            g_arrive = 0;                 // re-arm for next replay
            g_pos = 0.0; g_neg = 0.0;     // zero accumulators for this launch
            g_ticket = gridDim.x;         // dynamic tickets start after static assignment
            __threadfence();
            atomicAdd((unsigned*)&g_release, 1);
        } else {
            while (g_release < target) __nanosleep(64);
        }
        __threadfence();
    }
    __syncthreads();

    // ================= phase 1: half-tile (128x64) work loop =================
    float* spAI = (float*)(smem + PAR_OFF);
    float* spPI = spAI + 128;
    float* spQI = spPI + 128;
    int*   spLI = (int*)(spQI + 128);
    float* spAJ = (float*)(spLI + 128);     // 64 entries
    float* spPJ = spAJ + 64;
    float* spQJ = spPJ + 64;
    int*   spLJ = (int*)(spQJ + 64);
    float* red  = (float*)(smem + RED_OFF);
    unsigned* tick_s = (unsigned*)(red + 8);

    uint32_t csA = sbase + CS_OFF, csB = sbase + DS_OFF;
    int warp_m = wid & 1, warp_n = wid >> 1;

    float pos = 0.0f, neg = 0.0f;      // per-lane, carried across items
    unsigned t = blockIdx.x;

    while (t < NITEMS) {
        // item -> (I, J, half): half-tile covers rows I*128..+128, cols J*128+half*64..+64
        int ft = (int)(t >> 1), half = (int)(t & 1), I = 0;
        while (ft >= NT - I) { ft -= NT - I; I++; }
        int J = I + ft;
        int Ibase = I * 128, Jbase = J * 128 + half * 64;
        const char* baseI = (const char*)g_C + (size_t)Ibase * 512;
        const char* baseJ = (const char*)g_C + (size_t)Jbase * 512;

        __syncthreads();   // previous item's epilogue done reading smem

        // stage chunk 0: A = C(I) bytes [0,256) x128 rows, B = C(Jh) bytes [256,512) x64 rows
        {
            int row0 = tid >> 4, c16 = tid & 15;
            #pragma unroll
            for (int p = 0; p < 16; p++) {
                int r = row0 + p * 8;
                uint32_t dA = sbase + CS_OFF + r * PITCH + c16 * 16;
                const char* sA = baseI + r * 512 + c16 * 16;
                asm volatile("cp.async.ca.shared.global [%0], [%1], 16;" :: "r"(dA), "l"(sA));
            }
            #pragma unroll
            for (int p = 0; p < 8; p++) {
                int r = row0 + p * 8;
                uint32_t dB = sbase + DS_OFF + r * PITCH + c16 * 16;
                const char* sB = baseJ + r * 512 + 256 + c16 * 16;
                asm volatile("cp.async.ca.shared.global [%0], [%1], 16;" :: "r"(dB), "l"(sB));
            }
            asm volatile("cp.async.commit_group;" ::: "memory");
        }
        // params overlap the cp.async
        spAI[tid] = g_A8[Ibase + tid];
        spPI[tid] = g_P8[Ibase + tid];
        spQI[tid] = g_Q[Ibase + tid];
        spLI[tid] = labels[Ibase + tid];
        if (tid < 64) {
            spAJ[tid] = g_A8[Jbase + tid];
            spPJ[tid] = g_P8[Jbase + tid];
            spQJ[tid] = g_Q[Jbase + tid];
            spLJ[tid] = labels[Jbase + tid];
        }
        asm volatile("cp.async.wait_group 0;" ::: "memory");
        __syncthreads();

        uint32_t h[4][4][2];
        #pragma unroll
        for (int mi = 0; mi < 4; mi++)
            #pragma unroll
            for (int ni = 0; ni < 4; ni++) { h[mi][ni][0] = 0u; h[mi][ni][1] = 0u; }

        gemm_chunk(csA, csB, lane, warp_m, warp_n, h);

        // stage chunk 1: A = C(I) bytes [256,512), B = C(Jh) bytes [0,256)
        __syncthreads();
        {
            int row0 = tid >> 4, c16 = tid & 15;
            #pragma unroll
            for (int p = 0; p < 16; p++) {
                int r = row0 + p * 8;
                uint32_t dA = sbase + CS_OFF + r * PITCH + c16 * 16;
                const char* sA = baseI + r * 512 + 256 + c16 * 16;
                asm volatile("cp.async.ca.shared.global [%0], [%1], 16;" :: "r"(dA), "l"(sA));
            }
            #pragma unroll
            for (int p = 0; p < 8; p++) {
                int r = row0 + p * 8;
                uint32_t dB = sbase + DS_OFF + r * PITCH + c16 * 16;
                const char* sB = baseJ + r * 512 + c16 * 16;
                asm volatile("cp.async.ca.shared.global [%0], [%1], 16;" :: "r"(dB), "l"(sB));
            }
            asm volatile("cp.async.commit_group;" ::: "memory");
        }
        if (tid == 0) *tick_s = atomicAdd(&g_ticket, 1);   // fetch next item early
        asm volatile("cp.async.wait_group 0;" ::: "memory");
        __syncthreads();

        gemm_chunk(csA, csB, lane, warp_m, warp_n, h);

        // fused epilogue: sym/2 = 0.125*Gsum + A8_i + A8_j + P8_i*Q_j + P8_j*Q_i
        // sigmoid(sym) = 0.5 + 0.5*tanh(sym/2)
        const bool diag = (I == J);
        #pragma unroll
        for (int mi = 0; mi < 4; mi++) {
            #pragma unroll
            for (int k = 0; k < 2; k++) {
                int r = warp_m * 64 + mi * 16 + (lane >> 2) + k * 8;
                float RA = spAI[r], RP = spPI[r], RQ = spQI[r];
                int   RL = spLI[r];
                #pragma unroll
                for (int ni = 0; ni < 4; ni++) {
                    __half2 hv = *reinterpret_cast<__half2*>(&h[mi][ni][k]);
                    float2 f = __half22float2(hv);
                    int c0 = warp_n * 32 + ni * 8 + (lane & 3) * 2;
                    #pragma unroll
                    for (int e = 0; e < 2; e++) {
                        int c = c0 + e;
                        float vv = e ? f.y : f.x;
                        float s = fmaf(vv, 0.125f, RA);
                        s += spAJ[c];
                        s = fmaf(RP, spQJ[c], s);
                        s = fmaf(spPJ[c], RQ, s);
                        float sg = fmaf(ftanh(s), 0.5f, 0.5f);
                        // off-diag tile: every pair counts (global col > global row always).
                        // diag tile: count only strict upper triangle.
                        bool count = (!diag) || (half * 64 + c > r);
                        bool same  = (RL == spLJ[c]);
                        if (count) {
                            pos += same ? sg : 0.0f;
                            neg += same ? 0.0f : sg;
                        }
                    }
                }
            }
        }

        t = *tick_s;   // written before the post-stage sync -> coherent here
    }

    // ================= final reduce + output by last CTA =================
    #pragma unroll
    for (int off = 16; off; off >>= 1) {
        pos += __shfl_xor_sync(0xffffffffu, pos, off);
        neg += __shfl_xor_sync(0xffffffffu, neg, off);
    }
    __syncthreads();   // smem free for the reduce scratch
    if (lane == 0) { red[wid] = pos; red[4 + wid] = neg; }
    __syncthreads();
    if (tid == 0) {
        double P = 0.0, Nn = 0.0;
        #pragma unroll
        for (int w = 0; w < 4; w++) { P += (double)red[w]; Nn += (double)red[4 + w]; }
        atomicAdd(&g_pos, P);
        atomicAdd(&g_neg, Nn);
        __threadfence();
        unsigned d = atomicAdd(&g_done, 1);
        if (d == gridDim.x - 1) {
            double TP = 2.0 * atomicAdd(&g_pos, 0.0);   // read full totals
            double TN = 2.0 * atomicAdd(&g_neg, 0.0);
            const double inv = 1.0 / ((double)NB * (double)NB);
            out[0] = (float)(TP * inv);
            out[1] = (float)(TN * inv);
            out[2] = (float)TP;
            out[3] = (float)TN;
            g_done = 0;                                  // re-arm for next replay
        }
    }
}

// ---------------- launcher ----------------
extern "C" void kernel_launch(void* const* d_in, const int* in_sizes, int n_in,
                              void* d_out, int out_size) {
    (void)in_sizes; (void)n_in; (void)out_size;
    const float* mu     = (const float*)d_in[0];
    const float* var    = (const float*)d_in[1];
    const int*   labels = (const int*)d_in[2];
    float* out = (float*)d_out;

    cudaFuncSetAttribute(mega_kernel, cudaFuncAttributeMaxDynamicSharedMemorySize,
                         SMEM_BYTES);
    int occ = 0, sms = 0, dev = 0;
    cudaGetDevice(&dev);
    cudaOccupancyMaxActiveBlocksPerMultiprocessor(&occ, mega_kernel, 128, SMEM_BYTES);
    cudaDeviceGetAttribute(&sms, cudaDevAttrMultiProcessorCount, dev);
    int grid = occ * sms;
    if (grid > NITEMS) grid = NITEMS;
    if (grid < 1) grid = 1;

    mega_kernel<<<grid, 128, SMEM_BYTES>>>(mu, var, labels, out);
}